// round 12
// baseline (speedup 1.0000x reference)
#include <cuda_runtime.h>

#define NEGINF (-1.0e30f)

// ---------------- persistent scratch ----------------
__device__ float g_h [1568 * 128];
__device__ float g_q [1568 * 128];
__device__ float g_k [1568 * 128];
__device__ float g_v [1568 * 128];
__device__ float g_p [7 * 1568 * 128];   // attention partials per j-chunk
__device__ float g_h1[1568 * 256];
__device__ float g_r [1568 * 128];
__device__ float g_r2[1568 * 128];

// transposed weights [k][i]
__device__ float g_eWt  [256 * 128];
__device__ float g_qkvWt[6 * 128 * 128];
__device__ float g_f1t  [2 * 128 * 256];
__device__ float g_f2t  [2 * 256 * 128];

__device__ __forceinline__ void ma24(float (&a)[2][4], float2 x, float4 w) {
    float xs[2] = {x.x, x.y};
    float ws[4] = {w.x, w.y, w.z, w.w};
#pragma unroll
    for (int m = 0; m < 2; m++)
#pragma unroll
        for (int n = 0; n < 4; n++)
            a[m][n] = fmaxf(a[m][n], xs[m] + ws[n]);
}

__device__ __forceinline__ void ma22(float (&a)[2][2], float2 x, float2 w) {
    a[0][0] = fmaxf(a[0][0], x.x + w.x);
    a[0][1] = fmaxf(a[0][1], x.x + w.y);
    a[1][0] = fmaxf(a[1][0], x.y + w.x);
    a[1][1] = fmaxf(a[1][1], x.y + w.y);
}

// 4-deep pipelined tropical GEMM microkernels.  Load->use distance = one
// 4-iter body (~48 instr) > 29-cyc LDS latency.  Prefetches stay in bounds.
template<int XS, int WS, int K>
__device__ __forceinline__ void tg24(const float* xp, const float* wp,
                                     float (&acc)[2][4]) {
    float2 x0 = *(const float2*)(xp);
    float2 x1 = *(const float2*)(xp + XS);
    float2 x2 = *(const float2*)(xp + 2 * XS);
    float2 x3 = *(const float2*)(xp + 3 * XS);
    float4 w0 = *(const float4*)(wp);
    float4 w1 = *(const float4*)(wp + WS);
    float4 w2 = *(const float4*)(wp + 2 * WS);
    float4 w3 = *(const float4*)(wp + 3 * WS);
#pragma unroll 2
    for (int k = 0; k < K - 4; k += 4) {
        ma24(acc, x0, w0);
        x0 = *(const float2*)(xp + (k + 4) * XS);
        w0 = *(const float4*)(wp + (k + 4) * WS);
        ma24(acc, x1, w1);
        x1 = *(const float2*)(xp + (k + 5) * XS);
        w1 = *(const float4*)(wp + (k + 5) * WS);
        ma24(acc, x2, w2);
        x2 = *(const float2*)(xp + (k + 6) * XS);
        w2 = *(const float4*)(wp + (k + 6) * WS);
        ma24(acc, x3, w3);
        x3 = *(const float2*)(xp + (k + 7) * XS);
        w3 = *(const float4*)(wp + (k + 7) * WS);
    }
    ma24(acc, x0, w0); ma24(acc, x1, w1);
    ma24(acc, x2, w2); ma24(acc, x3, w3);
}

template<int XS, int WS, int K>
__device__ __forceinline__ void tg22(const float* xp, const float* wp,
                                     float (&acc)[2][2]) {
    float2 x0 = *(const float2*)(xp);
    float2 x1 = *(const float2*)(xp + XS);
    float2 x2 = *(const float2*)(xp + 2 * XS);
    float2 x3 = *(const float2*)(xp + 3 * XS);
    float2 w0 = *(const float2*)(wp);
    float2 w1 = *(const float2*)(wp + WS);
    float2 w2 = *(const float2*)(wp + 2 * WS);
    float2 w3 = *(const float2*)(wp + 3 * WS);
#pragma unroll 2
    for (int k = 0; k < K - 4; k += 4) {
        ma22(acc, x0, w0);
        x0 = *(const float2*)(xp + (k + 4) * XS);
        w0 = *(const float2*)(wp + (k + 4) * WS);
        ma22(acc, x1, w1);
        x1 = *(const float2*)(xp + (k + 5) * XS);
        w1 = *(const float2*)(wp + (k + 5) * WS);
        ma22(acc, x2, w2);
        x2 = *(const float2*)(xp + (k + 6) * XS);
        w2 = *(const float2*)(wp + (k + 6) * WS);
        ma22(acc, x3, w3);
        x3 = *(const float2*)(xp + (k + 7) * XS);
        w3 = *(const float2*)(wp + (k + 7) * WS);
    }
    ma22(acc, x0, w0); ma22(acc, x1, w1);
    ma22(acc, x2, w2); ma22(acc, x3, w3);
}

__device__ __forceinline__ void ostep(float (&o0)[8], float (&o1)[8],
                                      float2 s, float4 va, float4 vb) {
    float vv[8] = {va.x, va.y, va.z, va.w, vb.x, vb.y, vb.z, vb.w};
#pragma unroll
    for (int n = 0; n < 8; n++) {
        o0[n] = fmaxf(o0[n], s.x + vv[n]);
        o1[n] = fmaxf(o1[n], s.y + vv[n]);
    }
}

// ---------------------------------------------------------------------------
// Weight transpose: grid (32, 11), 256 threads.
// ---------------------------------------------------------------------------
__global__ void wtrans_kernel(const float* eW,
                              const float* q0, const float* k0, const float* v0,
                              const float* f10, const float* f20,
                              const float* q1, const float* k1, const float* v1,
                              const float* f11, const float* f21) {
    __shared__ float tile[32][33];
    const int id = blockIdx.y;
    const float* src; float* dst; int R, C;
    switch (id) {
        case 0:  src = eW;  dst = g_eWt;               R = 128; C = 256; break;
        case 1:  src = q0;  dst = g_qkvWt + 0 * 16384; R = 128; C = 128; break;
        case 2:  src = k0;  dst = g_qkvWt + 1 * 16384; R = 128; C = 128; break;
        case 3:  src = v0;  dst = g_qkvWt + 2 * 16384; R = 128; C = 128; break;
        case 4:  src = f10; dst = g_f1t;               R = 256; C = 128; break;
        case 5:  src = f20; dst = g_f2t;               R = 128; C = 256; break;
        case 6:  src = q1;  dst = g_qkvWt + 3 * 16384; R = 128; C = 128; break;
        case 7:  src = k1;  dst = g_qkvWt + 4 * 16384; R = 128; C = 128; break;
        case 8:  src = v1;  dst = g_qkvWt + 5 * 16384; R = 128; C = 128; break;
        case 9:  src = f11; dst = g_f1t + 32768;       R = 256; C = 128; break;
        default: src = f21; dst = g_f2t + 32768;       R = 128; C = 256; break;
    }
    const int tilesC = C >> 5;
    const int lin = blockIdx.x;
    if (lin >= tilesC * (R >> 5)) return;
    const int tr = lin / tilesC, tc = lin % tilesC;
    const int x = threadIdx.x & 31, y = threadIdx.x >> 5;
#pragma unroll
    for (int s = 0; s < 4; s++)
        tile[y + s * 8][x] = src[(tr * 32 + y + s * 8) * C + tc * 32 + x];
    __syncthreads();
#pragma unroll
    for (int s = 0; s < 4; s++)
        dst[(tc * 32 + y + s * 8) * R + tr * 32 + x] = tile[x][y + s * 8];
}

// ---------------------------------------------------------------------------
// Embed: patchify + tropical GEMM (K=256) + pos.  BM=8, BN=64.
// grid (196, 2), 128 threads, 2x2 tiles.
// ---------------------------------------------------------------------------
__global__ __launch_bounds__(128) void embed_kernel(const float* __restrict__ x,
                                                    const float* __restrict__ pos) {
    extern __shared__ float sm[];
    float* Xs = sm;            // [256][12]
    float* Ws = sm + 256 * 12; // [256][68]
    const int tid = threadIdx.x;
    const int r0 = blockIdx.x * 8;
    const int h0 = blockIdx.y * 64;

#pragma unroll
    for (int t = 0; t < 16; t++) {
        int lin = t * 128 + tid;
        int px = lin & 15, m = (lin >> 4) & 7, py = lin >> 7;
        int r = r0 + m;
        int b = r / 196, n = r % 196;
        int gy = n / 14, gx = n % 14;
        Xs[(py * 16 + px) * 12 + m] =
            x[(b * 224 + gy * 16 + py) * 224 + gx * 16 + px];
    }
#pragma unroll
    for (int t = 0; t < 32; t++) {
        int idx = t * 128 + tid;
        int k = idx >> 4, i4 = idx & 15;
        *(float4*)(Ws + k * 68 + i4 * 4) =
            *(const float4*)(g_eWt + k * 128 + h0 + i4 * 4);
    }
    __syncthreads();

    const int ty = tid >> 5, tx = tid & 31;
    float acc[2][2];
    acc[0][0] = acc[0][1] = acc[1][0] = acc[1][1] = NEGINF;

    tg22<12, 68, 256>(Xs + ty * 2, Ws + tx * 2, acc);

#pragma unroll
    for (int m = 0; m < 2; m++) {
        int r = r0 + ty * 2 + m;
        int nn = r % 196;
#pragma unroll
        for (int n = 0; n < 2; n++) {
            int col = h0 + tx * 2 + n;
            g_h[r * 128 + col] = acc[m][n] + pos[nn * 128 + col];
        }
    }
}

// ---------------------------------------------------------------------------
// QKV: rowmax(h) + GEMM on raw h, rmax subtracted in epilogue.
// BM=16, BN=128, 256 threads (2x4 tiles), grid (98, 3).
// ---------------------------------------------------------------------------
__global__ __launch_bounds__(256) void qkv_kernel(int layer) {
    extern __shared__ float sm[];
    float* Xs  = sm;                 // [128][20]
    float* Ws  = sm + 128 * 20;      // [128][132]
    float* red = Ws + 128 * 132;     // [16][16]
    float* rmx = red + 256;          // [16]
    const int tid = threadIdx.x;
    const int r0 = blockIdx.x * 16;
    const int which = blockIdx.y;

#pragma unroll
    for (int t = 0; t < 8; t++) {
        int lin = t * 256 + tid;
        int k = lin & 127, m = lin >> 7;
        Xs[k * 20 + m] = g_h[(r0 + m) * 128 + k];
    }
    const float* Wt = g_qkvWt + (layer * 3 + which) * 16384;
#pragma unroll
    for (int t = 0; t < 16; t++) {
        int idx = t * 256 + tid;
        int k = idx >> 5, i4 = idx & 31;
        *(float4*)(Ws + k * 132 + i4 * 4) =
            *(const float4*)(Wt + k * 128 + i4 * 4);
    }
    __syncthreads();
    {
        int row = tid >> 4, sub = tid & 15;
        float mx = NEGINF;
#pragma unroll
        for (int k = sub; k < 128; k += 16) mx = fmaxf(mx, Xs[k * 20 + row]);
        red[row * 16 + sub] = mx;
    }
    __syncthreads();
    if (tid < 16) {
        float mx = red[tid * 16];
#pragma unroll
        for (int s = 1; s < 16; s++) mx = fmaxf(mx, red[tid * 16 + s]);
        rmx[tid] = mx;
    }
    __syncthreads();

    const int ty = tid >> 5, tx = tid & 31;
    float acc[2][4];
#pragma unroll
    for (int m = 0; m < 2; m++)
#pragma unroll
        for (int n = 0; n < 4; n++) acc[m][n] = NEGINF;

    tg24<20, 132, 128>(Xs + ty * 2, Ws + tx * 4, acc);

    float* O = (which == 0) ? g_q : ((which == 1) ? g_k : g_v);
#pragma unroll
    for (int m = 0; m < 2; m++) {
        int row = ty * 2 + m;
        float rm = rmx[row];
        *(float4*)(O + (r0 + row) * 128 + tx * 4) =
            make_float4(acc[m][0] - rm, acc[m][1] - rm,
                        acc[m][2] - rm, acc[m][3] - rm);
    }
}

// ---------------------------------------------------------------------------
// Attention partial.  grid (7, 8, 7): 32 q-rows, batch, j-chunk of 32.
// 256 threads.  S: 32x32 (2x2/thread), O: 32x128 (2x8/thread), 4-deep pipes.
// ---------------------------------------------------------------------------
__global__ __launch_bounds__(256) void attnP_kernel() {
    extern __shared__ float sm[];
    float* Qs = sm;              // [128][36]
    float* Ks = sm + 4608;       // [128][34]
    float* Vs = Ks + 4352;       // [32][132]
    float* Ss = Vs + 4224;       // [32][36]
    const int tid = threadIdx.x;
    const int b = blockIdx.y;
    const int i0 = blockIdx.x * 32;
    const int j0 = blockIdx.z * 32;
    const int ty = tid >> 4, tx = tid & 15;   // ty 0..15, tx 0..15

#pragma unroll
    for (int t = 0; t < 16; t++) {
        int lin = t * 256 + tid;
        int d = lin & 127, i = lin >> 7;
        Qs[d * 36 + i] = (i0 + i < 196) ? g_q[(b * 196 + i0 + i) * 128 + d] : NEGINF;
    }
#pragma unroll
    for (int t = 0; t < 16; t++) {
        int lin = t * 256 + tid;
        int d = lin & 127, j = lin >> 7;
        bool ok = (j0 + j) < 196;
        int r = b * 196 + j0 + j;
        Ks[d * 34 + j] = ok ? g_k[r * 128 + d] : NEGINF;
        Vs[j * 132 + d] = ok ? g_v[r * 128 + d] : NEGINF;
    }
    __syncthreads();

    // S = max_d (Q + K): 32x32 tile, 2x2/thread, 4-deep pipeline
    float s4[2][2];
    s4[0][0] = s4[0][1] = s4[1][0] = s4[1][1] = NEGINF;
    tg22<36, 34, 128>(Qs + ty * 2, Ks + tx * 2, s4);

    Ss[(tx * 2 + 0) * 36 + ty * 2 + 0] = s4[0][0];
    Ss[(tx * 2 + 1) * 36 + ty * 2 + 0] = s4[0][1];
    Ss[(tx * 2 + 0) * 36 + ty * 2 + 1] = s4[1][0];
    Ss[(tx * 2 + 1) * 36 + ty * 2 + 1] = s4[1][1];
    __syncthreads();

    // O update: 32x128 tile, 2x8/thread, 4-deep pipeline over j (K=32)
    float o0[8], o1[8];
#pragma unroll
    for (int n = 0; n < 8; n++) { o0[n] = NEGINF; o1[n] = NEGINF; }
    {
        const float* sp = Ss + ty * 2;
        const float* vp = Vs + tx * 8;
        float2 s0 = *(const float2*)(sp);
        float2 s1 = *(const float2*)(sp + 36);
        float2 s2 = *(const float2*)(sp + 72);
        float2 s3 = *(const float2*)(sp + 108);
        float4 va0 = *(const float4*)(vp);
        float4 vb0 = *(const float4*)(vp + 4);
        float4 va1 = *(const float4*)(vp + 132);
        float4 vb1 = *(const float4*)(vp + 136);
        float4 va2 = *(const float4*)(vp + 264);
        float4 vb2 = *(const float4*)(vp + 268);
        float4 va3 = *(const float4*)(vp + 396);
        float4 vb3 = *(const float4*)(vp + 400);
#pragma unroll 2
        for (int j = 0; j < 28; j += 4) {
            ostep(o0, o1, s0, va0, vb0);
            s0  = *(const float2*)(sp + (j + 4) * 36);
            va0 = *(const float4*)(vp + (j + 4) * 132);
            vb0 = *(const float4*)(vp + (j + 4) * 132 + 4);
            ostep(o0, o1, s1, va1, vb1);
            s1  = *(const float2*)(sp + (j + 5) * 36);
            va1 = *(const float4*)(vp + (j + 5) * 132);
            vb1 = *(const float4*)(vp + (j + 5) * 132 + 4);
            ostep(o0, o1, s2, va2, vb2);
            s2  = *(const float2*)(sp + (j + 6) * 36);
            va2 = *(const float4*)(vp + (j + 6) * 132);
            vb2 = *(const float4*)(vp + (j + 6) * 132 + 4);
            ostep(o0, o1, s3, va3, vb3);
            s3  = *(const float2*)(sp + (j + 7) * 36);
            va3 = *(const float4*)(vp + (j + 7) * 132);
            vb3 = *(const float4*)(vp + (j + 7) * 132 + 4);
        }
        ostep(o0, o1, s0, va0, vb0);
        ostep(o0, o1, s1, va1, vb1);
        ostep(o0, o1, s2, va2, vb2);
        ostep(o0, o1, s3, va3, vb3);
    }

    float* P = g_p + blockIdx.z * 200704;
    int i_a = ty * 2, i_b = ty * 2 + 1;
    if (i0 + i_a < 196) {
        int base = (b * 196 + i0 + i_a) * 128 + tx * 8;
        *(float4*)(P + base)     = make_float4(o0[0], o0[1], o0[2], o0[3]);
        *(float4*)(P + base + 4) = make_float4(o0[4], o0[5], o0[6], o0[7]);
    }
    if (i0 + i_b < 196) {
        int base = (b * 196 + i0 + i_b) * 128 + tx * 8;
        *(float4*)(P + base)     = make_float4(o1[0], o1[1], o1[2], o1[3]);
        *(float4*)(P + base + 4) = make_float4(o1[4], o1[5], o1[6], o1[7]);
    }
}

// ---------------------------------------------------------------------------
// FF1: combine 7 attn partials + residual + pnorm (epilogue) + GEMM + tau.
// BM=16, BN=128, 256 threads (2x4 tiles), grid (98, 2).
// ---------------------------------------------------------------------------
__global__ __launch_bounds__(256) void ff1_kernel(int layer, const float* __restrict__ tau) {
    extern __shared__ float sm[];
    float* Xs  = sm;                     // [128][20]
    float* As  = sm + 2560;              // [128][20]
    float* Ws  = As + 2560;              // [128][132]
    float* red = Ws + 16896;             // [16][16]
    float* rmx = red + 256;              // [16]
    const int tid = threadIdx.x;
    const int r0 = blockIdx.x * 16;
    const int h0 = blockIdx.y * 128;

#pragma unroll
    for (int t = 0; t < 8; t++) {
        int lin = t * 256 + tid;
        int k = lin & 127, m = lin >> 7;
        int gi = (r0 + m) * 128 + k;
        Xs[k * 20 + m] = g_h[gi];
        float a0 = fmaxf(g_p[gi],              g_p[gi + 200704]);
        float a1 = fmaxf(g_p[gi + 2 * 200704], g_p[gi + 3 * 200704]);
        float a2 = fmaxf(g_p[gi + 4 * 200704], g_p[gi + 5 * 200704]);
        float a3 = g_p[gi + 6 * 200704];
        As[k * 20 + m] = fmaxf(fmaxf(a0, a1), fmaxf(a2, a3));
    }
    const float* Wt = g_f1t + layer * 32768;
#pragma unroll
    for (int t = 0; t < 16; t++) {
        int idx = t * 256 + tid;
        int k = idx >> 5, i4 = idx & 31;
        *(float4*)(Ws + k * 132 + i4 * 4) =
            *(const float4*)(Wt + k * 256 + h0 + i4 * 4);
    }
    __syncthreads();
    // rowmax(a)
    {
        int row = tid >> 4, sub = tid & 15;
        float mx = NEGINF;
#pragma unroll
        for (int k = sub; k < 128; k += 16) mx = fmaxf(mx, As[k * 20 + row]);
        red[row * 16 + sub] = mx;
    }
    __syncthreads();
    if (tid < 16) {
        float mx = red[tid * 16];
#pragma unroll
        for (int s = 1; s < 16; s++) mx = fmaxf(mx, red[tid * 16 + s]);
        rmx[tid] = mx;
    }
    __syncthreads();
    // h' = max(h, a - rma); write back once
#pragma unroll
    for (int t = 0; t < 8; t++) {
        int lin = t * 256 + tid;
        int k = lin & 127, m = lin >> 7;
        float v = fmaxf(Xs[k * 20 + m], As[k * 20 + m] - rmx[m]);
        Xs[k * 20 + m] = v;
        if (blockIdx.y == 0) g_h[(r0 + m) * 128 + k] = v;
    }
    __syncthreads();
    // rowmax(h') for epilogue subtraction
    {
        int row = tid >> 4, sub = tid & 15;
        float mx = NEGINF;
#pragma unroll
        for (int k = sub; k < 128; k += 16) mx = fmaxf(mx, Xs[k * 20 + row]);
        red[row * 16 + sub] = mx;
    }
    __syncthreads();
    if (tid < 16) {
        float mx = red[tid * 16];
#pragma unroll
        for (int s = 1; s < 16; s++) mx = fmaxf(mx, red[tid * 16 + s]);
        rmx[tid] = mx;
    }
    __syncthreads();

    const int ty = tid >> 5, tx = tid & 31;
    float acc[2][4];
#pragma unroll
    for (int m = 0; m < 2; m++)
#pragma unroll
        for (int n = 0; n < 4; n++) acc[m][n] = NEGINF;

    tg24<20, 132, 128>(Xs + ty * 2, Ws + tx * 4, acc);

    const float tv = tau[0];
#pragma unroll
    for (int m = 0; m < 2; m++) {
        int row = ty * 2 + m;
        float rm = rmx[row];
        *(float4*)(g_h1 + (r0 + row) * 256 + h0 + tx * 4) =
            make_float4(fmaxf(acc[m][0] - rm, tv), fmaxf(acc[m][1] - rm, tv),
                        fmaxf(acc[m][2] - rm, tv), fmaxf(acc[m][3] - rm, tv));
    }
}

// ---------------------------------------------------------------------------
// FF2 GEMM (raw, K-split 2): BM=16, BN=64, K=128 per CTA, 256 threads (2x2).
// grid (98, 2, 2): y = n-half, z = k-half -> g_r / g_r2.
// ---------------------------------------------------------------------------
__global__ __launch_bounds__(256) void ff2_kernel(int layer) {
    extern __shared__ float sm[];
    float* Xs = sm;            // [128][20]
    float* Ws = sm + 2560;     // [128][68]
    const int tid = threadIdx.x;
    const int r0 = blockIdx.x * 16;
    const int h0 = blockIdx.y * 64;
    const int k0 = blockIdx.z * 128;

#pragma unroll
    for (int t = 0; t < 8; t++) {
        int lin = t * 256 + tid;
        int k = lin & 127, m = lin >> 7;
        Xs[k * 20 + m] = g_h1[(r0 + m) * 256 + k0 + k];
    }
    const float* Wt = g_f2t + layer * 32768;
#pragma unroll
    for (int t = 0; t < 8; t++) {
        int idx = t * 256 + tid;
        int k = idx >> 4, i4 = idx & 15;
        *(float4*)(Ws + k * 68 + i4 * 4) =
            *(const float4*)(Wt + (k0 + k) * 128 + h0 + i4 * 4);
    }
    __syncthreads();

    const int ty = tid >> 5, tx = tid & 31;
    float acc[2][2];
    acc[0][0] = acc[0][1] = acc[1][0] = acc[1][1] = NEGINF;

    tg22<20, 68, 128>(Xs + ty * 2, Ws + tx * 2, acc);

    float* O = blockIdx.z ? g_r2 : g_r;
#pragma unroll
    for (int m = 0; m < 2; m++) {
        int r = r0 + ty * 2 + m;
        *(float2*)(O + r * 128 + h0 + tx * 2) = make_float2(acc[m][0], acc[m][1]);
    }
}

// ---------------------------------------------------------------------------
// FF2 combine: out = max(r, r2); rowmax; h = max(h, out - rm). grid 196, 256.
// ---------------------------------------------------------------------------
__global__ void comb2_kernel() {
    const int w = threadIdx.x >> 5, lane = threadIdx.x & 31;
    const int r = blockIdx.x * 8 + w;
    float4 a = *(const float4*)(g_r  + r * 128 + lane * 4);
    float4 c = *(const float4*)(g_r2 + r * 128 + lane * 4);
    float4 v = make_float4(fmaxf(a.x, c.x), fmaxf(a.y, c.y),
                           fmaxf(a.z, c.z), fmaxf(a.w, c.w));
    float m = fmaxf(fmaxf(v.x, v.y), fmaxf(v.z, v.w));
#pragma unroll
    for (int s = 16; s; s >>= 1) m = fmaxf(m, __shfl_xor_sync(0xffffffffu, m, s));
    float4 h = *(float4*)(g_h + r * 128 + lane * 4);
    h.x = fmaxf(h.x, v.x - m);
    h.y = fmaxf(h.y, v.y - m);
    h.z = fmaxf(h.z, v.z - m);
    h.w = fmaxf(h.w, v.w - m);
    *(float4*)(g_h + r * 128 + lane * 4) = h;
}

// ---------------------------------------------------------------------------
// Pool + head.  grid (8, 8), 128 threads.
// ---------------------------------------------------------------------------
__global__ void head_kernel(const float* __restrict__ hW,
                            const float* __restrict__ ls,
                            float* __restrict__ out) {
    __shared__ float pooled[128];
    const int b = blockIdx.x, ct = blockIdx.y, tid = threadIdx.x;

    const float* hp = g_h + (b * 196) * 128 + tid;
    float m0 = NEGINF, m1 = NEGINF, m2 = NEGINF, m3 = NEGINF;
#pragma unroll 4
    for (int n = 0; n < 196; n += 4) {
        m0 = fmaxf(m0, hp[(n + 0) * 128]);
        m1 = fmaxf(m1, hp[(n + 1) * 128]);
        m2 = fmaxf(m2, hp[(n + 2) * 128]);
        m3 = fmaxf(m3, hp[(n + 3) * 128]);
    }
    pooled[tid] = fmaxf(fmaxf(m0, m1), fmaxf(m2, m3));
    __syncthreads();

    int c = ct * 125 + tid;
    if (tid < 125) {
        const float* w = hW + c * 128;
        float a = NEGINF;
#pragma unroll 8
        for (int d = 0; d < 128; d++) a = fmaxf(a, pooled[d] + w[d]);
        out[b * 1000 + c] = a * ls[0];
    }
}

// ---------------------------------------------------------------------------
static const int SMEM_EMBED = (256 * 12 + 256 * 68) * 4;
static const int SMEM_QKV   = (128 * 20 + 128 * 132 + 256 + 16) * 4;
static const int SMEM_ATTN  = (4608 + 4352 + 4224 + 32 * 36) * 4;
static const int SMEM_FF1   = (128 * 20 * 2 + 128 * 132 + 256 + 16) * 4;
static const int SMEM_FF2   = (128 * 20 + 128 * 68) * 4;

extern "C" void kernel_launch(void* const* d_in, const int* in_sizes, int n_in,
                              void* d_out, int out_size) {
    const float* x   = (const float*)d_in[0];
    const float* eW  = (const float*)d_in[1];
    const float* pos = (const float*)d_in[2];
    const float* qW[2]  = {(const float*)d_in[3],  (const float*)d_in[9]};
    const float* kW[2]  = {(const float*)d_in[4],  (const float*)d_in[10]};
    const float* vW[2]  = {(const float*)d_in[5],  (const float*)d_in[11]};
    const float* f1W[2] = {(const float*)d_in[6],  (const float*)d_in[12]};
    const float* f2W[2] = {(const float*)d_in[7],  (const float*)d_in[13]};
    const float* tau[2] = {(const float*)d_in[8],  (const float*)d_in[14]};
    const float* hW  = (const float*)d_in[15];
    const float* ls  = (const float*)d_in[16];
    float* out = (float*)d_out;

    cudaFuncSetAttribute(embed_kernel, cudaFuncAttributeMaxDynamicSharedMemorySize, SMEM_EMBED);
    cudaFuncSetAttribute(qkv_kernel,   cudaFuncAttributeMaxDynamicSharedMemorySize, SMEM_QKV);
    cudaFuncSetAttribute(attnP_kernel, cudaFuncAttributeMaxDynamicSharedMemorySize, SMEM_ATTN);
    cudaFuncSetAttribute(ff1_kernel,   cudaFuncAttributeMaxDynamicSharedMemorySize, SMEM_FF1);
    cudaFuncSetAttribute(ff2_kernel,   cudaFuncAttributeMaxDynamicSharedMemorySize, SMEM_FF2);

    wtrans_kernel<<<dim3(32, 11), 256>>>(eW, qW[0], kW[0], vW[0], f1W[0], f2W[0],
                                         qW[1], kW[1], vW[1], f1W[1], f2W[1]);
    embed_kernel<<<dim3(196, 2), 128, SMEM_EMBED>>>(x, pos);
    for (int l = 0; l < 2; l++) {
        qkv_kernel<<<dim3(98, 3), 256, SMEM_QKV>>>(l);
        attnP_kernel<<<dim3(7, 8, 7), 256, SMEM_ATTN>>>();
        ff1_kernel<<<dim3(98, 2), 256, SMEM_FF1>>>(l, tau[l]);
        ff2_kernel<<<dim3(98, 2, 2), 256, SMEM_FF2>>>(l);
        comb2_kernel<<<196, 256>>>();
    }
    head_kernel<<<dim3(8, 8), 128>>>(hW, ls, out);
}